// round 16
// baseline (speedup 1.0000x reference)
#include <cuda_runtime.h>
#include <cstdint>
#include <math.h>

#define NXC 49152
#define NYC 50000
#define NT_Y 391
#define NY_PAD (NT_Y*128)          // 50048
#define CDIM 128
#define KTOP 10
#define DEPTH 12
#define NCAND 48                   // 4 col-classes * 12
#define NXK (NXC*KTOP)
#define INV_TAU 20.0f

#define MTILES (NXC/64)            // 768 CTAs, 64 rows each

#define NPACK_X (MTILES*2048)      // A-image uint4 count (32KB / 64-row tile)
#define NPACK_Y (NT_Y*4096)        // B-image uint4 count (64KB / 128-col tile)

#define RESCORE_SMEM 25664         // (128 + 48*129 + 48 + 48) * 4 bytes

// ---------------- device scratch ----------------
__device__ float g_x32[NXC*CDIM];      // normalized x, row-major (exact fp32)
__device__ float g_y32[NY_PAD*CDIM];   // normalized y, row-major, zero-padded
__device__ uint4 g_xA[NPACK_X];        // tf32 A fragment images
__device__ uint4 g_yB[NPACK_Y];        // tf32 B fragment images
__device__ int   g_candI[NXC*NCAND];   // candidate cols per row

// ---------------- helpers ----------------
__device__ __forceinline__ unsigned tf32_of(float f) {
    unsigned u; asm("cvt.rna.tf32.f32 %0, %1;" : "=r"(u) : "f"(f)); return u;
}
__device__ __forceinline__ void mma_tf32(float (&c)[4], const uint4& a, unsigned b0, unsigned b1) {
    asm volatile(
        "mma.sync.aligned.m16n8k8.row.col.f32.tf32.tf32.f32 "
        "{%0,%1,%2,%3}, {%4,%5,%6,%7}, {%8,%9}, {%0,%1,%2,%3};"
        : "+f"(c[0]), "+f"(c[1]), "+f"(c[2]), "+f"(c[3])
        : "r"(a.x), "r"(a.y), "r"(a.z), "r"(a.w), "r"(b0), "r"(b1));
}
__device__ __forceinline__ void insert12(float (&tv)[12], int (&ti)[12], float v, int j) {
    tv[11] = v; ti[11] = j;
#pragma unroll
    for (int s = 11; s > 0; --s) {
        bool sw = (tv[s] > tv[s-1]) || (tv[s] == tv[s-1] && ti[s] < ti[s-1]);
        if (sw) {
            float fv = tv[s]; tv[s] = tv[s-1]; tv[s-1] = fv;
            int   fi = ti[s]; ti[s] = ti[s-1]; ti[s-1] = fi;
        }
    }
}
__device__ __forceinline__ void insert10(float (&tv)[10], int (&ti)[10], float v, int j) {
    tv[9] = v; ti[9] = j;
#pragma unroll
    for (int s = 9; s > 0; --s) {
        bool sw = (tv[s] > tv[s-1]) || (tv[s] == tv[s-1] && ti[s] < ti[s-1]);
        if (sw) {
            float fv = tv[s]; tv[s] = tv[s-1]; tv[s-1] = fv;
            int   fi = ti[s]; ti[s] = ti[s-1]; ti[s-1] = fi;
        }
    }
}

// ---------------- normalize (EXACT same arithmetic as the passing chain) ----------------
__global__ void norm_x_kernel(const float* __restrict__ in) {
    int warp = (blockIdx.x * blockDim.x + threadIdx.x) >> 5;
    int lane = threadIdx.x & 31;
    if (warp >= NXC) return;
    float4 v = *(const float4*)&in[warp * CDIM + lane * 4];
    float ss = v.x*v.x + v.y*v.y + v.z*v.z + v.w*v.w;
#pragma unroll
    for (int o = 16; o > 0; o >>= 1) ss += __shfl_xor_sync(0xffffffffu, ss, o);
    float inv = 1.0f / fmaxf(sqrtf(ss), 1e-12f);
    *(float4*)&g_x32[warp * CDIM + lane * 4] = make_float4(v.x*inv, v.y*inv, v.z*inv, v.w*inv);
}
__global__ void norm_y_kernel(const float* __restrict__ in) {
    int warp = (blockIdx.x * blockDim.x + threadIdx.x) >> 5;
    int lane = threadIdx.x & 31;
    if (warp >= NY_PAD) return;
    if (warp >= NYC) {
        *(float4*)&g_y32[warp * CDIM + lane * 4] = make_float4(0.f, 0.f, 0.f, 0.f);
        return;
    }
    float4 v = *(const float4*)&in[warp * CDIM + lane * 4];
    float ss = v.x*v.x + v.y*v.y + v.z*v.z + v.w*v.w;
#pragma unroll
    for (int o = 16; o > 0; o >>= 1) ss += __shfl_xor_sync(0xffffffffu, ss, o);
    float inv = 1.0f / fmaxf(sqrtf(ss), 1e-12f);
    *(float4*)&g_y32[warp * CDIM + lane * 4] = make_float4(v.x*inv, v.y*inv, v.z*inv, v.w*inv);
}

// ---------------- fused tf32 fragment packing (single launch -> gemm is launch #4) ----
// A image per 64-row mtile: uint4 i = mt*2048 + (w*16 + k8)*32 + lane
//   g=lane>>2, t=lane&3; r=mt*64+w*16+g; k=k8*8+t
//   a = { A[r][k], A[r+8][k], A[r][k+4], A[r+8][k+4] }
// B image per 128-col ytile: uint4 j = yt*4096 + (k8*8 + p)*32 + lane   (p = 0..7)
//   n_e=yt*128+p*16+g; n_o=n_e+8; k=k8*8+t
//   b = { B[n_e][k], B[n_e][k+4], B[n_o][k], B[n_o][k+4] }
__global__ void pack_xy_frag() {
    int i = blockIdx.x * blockDim.x + threadIdx.x;
    if (i < NPACK_X) {
        int lane = i & 31;
        int k8   = (i >> 5) & 15;
        int w    = (i >> 9) & 3;
        int mt   = i >> 11;
        int g = lane >> 2, t = lane & 3;
        int r = mt * 64 + w * 16 + g;
        int k = k8 * 8 + t;
        uint4 a;
        a.x = tf32_of(g_x32[r * CDIM + k]);
        a.y = tf32_of(g_x32[(r + 8) * CDIM + k]);
        a.z = tf32_of(g_x32[r * CDIM + k + 4]);
        a.w = tf32_of(g_x32[(r + 8) * CDIM + k + 4]);
        g_xA[i] = a;
        return;
    }
    int j = i - NPACK_X;
    if (j >= NPACK_Y) return;
    int lane = j & 31;
    int p    = (j >> 5) & 7;
    int k8   = (j >> 8) & 15;
    int yt   = j >> 12;
    int g = lane >> 2, t = lane & 3;
    int ce = yt * 128 + p * 16 + g;
    int co = ce + 8;
    int k = k8 * 8 + t;
    uint4 b;
    b.x = tf32_of(g_y32[ce * CDIM + k]);
    b.y = tf32_of(g_y32[ce * CDIM + k + 4]);
    b.z = tf32_of(g_y32[co * CDIM + k]);
    b.w = tf32_of(g_y32[co * CDIM + k + 4]);
    g_yB[j] = b;
}

// ---------------- 32KB A-tile cp.async (128 threads) ----------------
__device__ __forceinline__ void cp32k(char* dst_sm, const char* src, int tid) {
#pragma unroll
    for (int i = 0; i < 16; i++) {
        int off = (tid + 128 * i) * 16;
        unsigned s = (unsigned)__cvta_generic_to_shared(dst_sm + off);
        asm volatile("cp.async.cg.shared.global [%0], [%1], 16;" :: "r"(s), "l"(src + off));
    }
    asm volatile("cp.async.commit_group;" ::: "memory");
}

// ---------------- tf32 mma GEMM, occ-3, barrier-free, LDG-streamed B ----------------
__global__ __launch_bounds__(128, 3) void gemm_topk_kernel() {
    extern __shared__ char sm[];
    const int tid  = threadIdx.x;
    const int w    = tid >> 5;
    const int lane = tid & 31;
    const int g    = lane >> 2;
    const int t4   = lane & 3;
    const int mtile = blockIdx.x;

    cp32k(sm, (const char*)(g_xA + (size_t)mtile * 2048), tid);
    asm volatile("cp.async.wait_group 0;" ::: "memory");
    __syncthreads();                                   // only barrier in the kernel

    const uint4* AsW = (const uint4*)sm + w * 16 * 32; // this warp's m-frag, 16 k8 slabs

    float tvA[12], tvB[12]; int tiA[12], tiB[12];
#pragma unroll
    for (int q = 0; q < 12; q++) {
        tvA[q] = tvB[q] = -__int_as_float(0x7f800000);
        tiA[q] = tiB[q] = 0x7fffffff;
    }

    for (int t = 0; t < NT_Y; t++) {
        const uint4* __restrict__ Bt = g_yB + (size_t)t * 4096;

        uint4 b0[4], b1[4];
#pragma unroll
        for (int p = 0; p < 4; p++) b0[p] = Bt[p * 32 + lane];   // k8=0 half0

        float acc[16][4];
#pragma unroll
        for (int nf = 0; nf < 16; nf++)
#pragma unroll
            for (int q = 0; q < 4; q++) acc[nf][q] = 0.0f;

#pragma unroll
        for (int k8 = 0; k8 < 16; k8++) {
            uint4 a = AsW[k8 * 32 + lane];
#pragma unroll
            for (int p = 0; p < 4; p++) b1[p] = Bt[(k8 * 8 + 4 + p) * 32 + lane];  // half1
            // mma on half0 (nf 0..7) — b0 loaded 8 mmas ago
#pragma unroll
            for (int p = 0; p < 4; p++) {
                mma_tf32(acc[2*p],     a, b0[p].x, b0[p].y);
                mma_tf32(acc[2*p + 1], a, b0[p].z, b0[p].w);
            }
            if (k8 < 15) {
#pragma unroll
                for (int p = 0; p < 4; p++) b0[p] = Bt[((k8 + 1) * 8 + p) * 32 + lane];
            }
            // mma on half1 (nf 8..15) — b1 loaded 8 mmas ago
#pragma unroll
            for (int p = 0; p < 4; p++) {
                mma_tf32(acc[8 + 2*p], a, b1[p].x, b1[p].y);
                mma_tf32(acc[9 + 2*p], a, b1[p].z, b1[p].w);
            }
        }

        // scan: thread owns rows (g, g+8); cols nf*8 + t4*2 + {0,1}
        int n0 = t * 128 + t4 * 2;
#pragma unroll
        for (int nf = 0; nf < 16; nf++) {
            int j0 = n0 + nf * 8;
            float v0 = acc[nf][0], v1 = acc[nf][1], v2 = acc[nf][2], v3 = acc[nf][3];
            if (v0 > tvA[11] && j0 < NYC)     insert12(tvA, tiA, v0, j0);
            if (v1 > tvA[11] && j0 + 1 < NYC) insert12(tvA, tiA, v1, j0 + 1);
            if (v2 > tvB[11] && j0 < NYC)     insert12(tvB, tiB, v2, j0);
            if (v3 > tvB[11] && j0 + 1 < NYC) insert12(tvB, tiB, v3, j0 + 1);
        }
    }

    int mA = mtile * 64 + w * 16 + g;
    int mB = mA + 8;
#pragma unroll
    for (int q = 0; q < 12; q++) {
        g_candI[mA * NCAND + t4 * 12 + q] = tiA[q];
        g_candI[mB * NCAND + t4 * 12 + q] = tiB[q];
    }
}

// ---------------- exact fp32 rescore (bitwise-identical chain) + softmax + COO ----------------
__global__ __launch_bounds__(128) void rescore_kernel(float* __restrict__ out) {
    extern __shared__ float rs[];
    float* xrow  = rs;                        // 128
    float* yrows = rs + 128;                  // 48 * 129 (pitch 129 -> conflict-free)
    float* vals  = yrows + 48 * 129;          // 48
    int*   cols  = (int*)(vals + 48);         // 48   (total 6416 floats = 25664 B)

    const int m = blockIdx.x;
    const int tid = threadIdx.x;

    if (tid < 128) xrow[tid] = g_x32[m * CDIM + tid];
    if (tid < 48)  cols[tid] = g_candI[m * NCAND + tid];
    __syncthreads();

    for (int i = tid; i < 48 * 32; i += 128) {
        int c = i >> 5, p = i & 31;
        float4 v = *(const float4*)&g_y32[(size_t)cols[c] * CDIM + p * 4];
        float* dst = &yrows[c * 129 + p * 4];
        dst[0] = v.x; dst[1] = v.y; dst[2] = v.z; dst[3] = v.w;
    }
    __syncthreads();

    if (tid < 48) {
        float s = 0.0f;
        const float* yr = &yrows[tid * 129];
#pragma unroll 16
        for (int k = 0; k < 128; k++) s = fmaf(xrow[k], yr[k], s);
        vals[tid] = s;
    }
    __syncthreads();

    if (tid == 0) {
        float tv[10]; int tix[10];
#pragma unroll
        for (int q = 0; q < 10; q++) { tv[q] = -__int_as_float(0x7f800000); tix[q] = 0x7fffffff; }
        for (int c = 0; c < 48; c++) {
            float v = vals[c]; int j = cols[c];
            if (v > tv[9] || (v == tv[9] && j < tix[9])) insert10(tv, tix, v, j);
        }
        float mx = tv[0];
        float e[10], sum = 0.0f;
#pragma unroll
        for (int q = 0; q < 10; q++) { e[q] = expf((tv[q] - mx) * INV_TAU); sum += e[q]; }
        float inv = 1.0f / sum;
#pragma unroll
        for (int q = 0; q < 10; q++) {
            out[m * 10 + q]           = e[q] * inv;
            out[NXK + m * 10 + q]     = (float)m;
            out[2 * NXK + m * 10 + q] = (float)tix[q];
        }
    }
}

// ---------------- launch ----------------
extern "C" void kernel_launch(void* const* d_in, const int* in_sizes, int n_in,
                              void* d_out, int out_size) {
    const float* fx = (const float*)d_in[0];
    const float* fy = (const float*)d_in[1];
    if (n_in >= 2 && in_sizes[0] == NYC * CDIM && in_sizes[1] == NXC * CDIM) {
        const float* t = fx; fx = fy; fy = t;
    }
    float* outF = (float*)d_out;

    cudaFuncSetAttribute(rescore_kernel,
                         cudaFuncAttributeMaxDynamicSharedMemorySize, RESCORE_SMEM);

    norm_x_kernel<<<NXC / 8, 256>>>(fx);                                  // launch 1
    norm_y_kernel<<<NY_PAD / 8, 256>>>(fy);                               // launch 2
    pack_xy_frag<<<(NPACK_X + NPACK_Y + 255) / 256, 256>>>();             // launch 3
    gemm_topk_kernel<<<MTILES, 128, 32768>>>();                           // launch 4 (ncu target)
    rescore_kernel<<<NXC, 128, RESCORE_SMEM>>>(outF);                     // launch 5
}

// round 17
// speedup vs baseline: 1.5852x; 1.5852x over previous
#include <cuda_runtime.h>
#include <cstdint>
#include <math.h>

#define NXC 49152
#define NYC 50000
#define NT_Y 391
#define NY_PAD (NT_Y*128)          // 50048
#define CDIM 128
#define KTOP 10
#define NCAND 40                   // 4 col-classes * 10
#define NXK (NXC*KTOP)
#define INV_TAU 20.0f

#define MTILES (NXC/32)            // 1536 CTAs, 32 rows each

#define NPACK_X (MTILES*1024)      // A-image uint4 count (16KB / 32-row tile)
#define NPACK_Y (NT_Y*4096)        // B-image uint4 count (64KB / 128-col tile)

#define RESCORE_SMEM 21472         // (128 + 40*129 + 40 + 40) * 4 bytes

// ---------------- device scratch ----------------
__device__ float g_x32[NXC*CDIM];      // normalized x, row-major (exact fp32)
__device__ float g_y32[NY_PAD*CDIM];   // normalized y, row-major, zero-padded
__device__ uint4 g_xA[NPACK_X];        // tf32 A fragment images
__device__ uint4 g_yB[NPACK_Y];        // tf32 B fragment images
__device__ int   g_candI[NXC*NCAND];   // candidate cols per row

// ---------------- helpers ----------------
__device__ __forceinline__ unsigned tf32_of(float f) {
    unsigned u; asm("cvt.rna.tf32.f32 %0, %1;" : "=r"(u) : "f"(f)); return u;
}
__device__ __forceinline__ void mma_tf32(float (&c)[4], const uint4& a, unsigned b0, unsigned b1) {
    asm volatile(
        "mma.sync.aligned.m16n8k8.row.col.f32.tf32.tf32.f32 "
        "{%0,%1,%2,%3}, {%4,%5,%6,%7}, {%8,%9}, {%0,%1,%2,%3};"
        : "+f"(c[0]), "+f"(c[1]), "+f"(c[2]), "+f"(c[3])
        : "r"(a.x), "r"(a.y), "r"(a.z), "r"(a.w), "r"(b0), "r"(b1));
}
__device__ __forceinline__ void insert10(float (&tv)[10], int (&ti)[10], float v, int j) {
    tv[9] = v; ti[9] = j;
#pragma unroll
    for (int s = 9; s > 0; --s) {
        bool sw = (tv[s] > tv[s-1]) || (tv[s] == tv[s-1] && ti[s] < ti[s-1]);
        if (sw) {
            float fv = tv[s]; tv[s] = tv[s-1]; tv[s-1] = fv;
            int   fi = ti[s]; ti[s] = ti[s-1]; ti[s-1] = fi;
        }
    }
}

// ---------------- normalize (EXACT same arithmetic as the passing chain) ----------------
__global__ void norm_x_kernel(const float* __restrict__ in) {
    int warp = (blockIdx.x * blockDim.x + threadIdx.x) >> 5;
    int lane = threadIdx.x & 31;
    if (warp >= NXC) return;
    float4 v = *(const float4*)&in[warp * CDIM + lane * 4];
    float ss = v.x*v.x + v.y*v.y + v.z*v.z + v.w*v.w;
#pragma unroll
    for (int o = 16; o > 0; o >>= 1) ss += __shfl_xor_sync(0xffffffffu, ss, o);
    float inv = 1.0f / fmaxf(sqrtf(ss), 1e-12f);
    *(float4*)&g_x32[warp * CDIM + lane * 4] = make_float4(v.x*inv, v.y*inv, v.z*inv, v.w*inv);
}
__global__ void norm_y_kernel(const float* __restrict__ in) {
    int warp = (blockIdx.x * blockDim.x + threadIdx.x) >> 5;
    int lane = threadIdx.x & 31;
    if (warp >= NY_PAD) return;
    if (warp >= NYC) {
        *(float4*)&g_y32[warp * CDIM + lane * 4] = make_float4(0.f, 0.f, 0.f, 0.f);
        return;
    }
    float4 v = *(const float4*)&in[warp * CDIM + lane * 4];
    float ss = v.x*v.x + v.y*v.y + v.z*v.z + v.w*v.w;
#pragma unroll
    for (int o = 16; o > 0; o >>= 1) ss += __shfl_xor_sync(0xffffffffu, ss, o);
    float inv = 1.0f / fmaxf(sqrtf(ss), 1e-12f);
    *(float4*)&g_y32[warp * CDIM + lane * 4] = make_float4(v.x*inv, v.y*inv, v.z*inv, v.w*inv);
}

// ---------------- fused tf32 fragment packing ----------------
// A image per 32-row mtile: uint4 i = mt*1024 + (f*16 + k8)*32 + lane
//   lane=i&31, k8=(i>>5)&15, f=(i>>9)&1, mt=i>>10
//   g=lane>>2, t=lane&3; r=mt*32+f*16+g; k=k8*8+t
//   a = { A[r][k], A[r+8][k], A[r][k+4], A[r+8][k+4] }
// B image per 128-col ytile (PROVEN in R15/16): uint4 j = yt*4096 + (k8*8 + p)*32 + lane
//   lane=j&31, p=(j>>5)&7, k8=(j>>8)&15, yt=j>>12
//   n_e=yt*128+p*16+g; n_o=n_e+8; k=k8*8+t
__global__ void pack_xy_frag() {
    int i = blockIdx.x * blockDim.x + threadIdx.x;
    if (i < NPACK_X) {
        int lane = i & 31;
        int k8   = (i >> 5) & 15;
        int f    = (i >> 9) & 1;
        int mt   = i >> 10;
        int g = lane >> 2, t = lane & 3;
        int r = mt * 32 + f * 16 + g;
        int k = k8 * 8 + t;
        uint4 a;
        a.x = tf32_of(g_x32[r * CDIM + k]);
        a.y = tf32_of(g_x32[(r + 8) * CDIM + k]);
        a.z = tf32_of(g_x32[r * CDIM + k + 4]);
        a.w = tf32_of(g_x32[(r + 8) * CDIM + k + 4]);
        g_xA[i] = a;
        return;
    }
    int j = i - NPACK_X;
    if (j >= NPACK_Y) return;
    int lane = j & 31;
    int p    = (j >> 5) & 7;
    int k8   = (j >> 8) & 15;
    int yt   = j >> 12;
    int g = lane >> 2, t = lane & 3;
    int ce = yt * 128 + p * 16 + g;
    int co = ce + 8;
    int k = k8 * 8 + t;
    uint4 b;
    b.x = tf32_of(g_y32[ce * CDIM + k]);
    b.y = tf32_of(g_y32[ce * CDIM + k + 4]);
    b.z = tf32_of(g_y32[co * CDIM + k]);
    b.w = tf32_of(g_y32[co * CDIM + k + 4]);
    g_yB[j] = b;
}

// ---------------- k-split tf32 mma GEMM, occ-3, smem-B, in-register top-10 ----------------
// CTA = 32 rows; warps: mf = w&1 (m-frag), kh = w>>1 (k-half).
// smem = 64KB B tile only; partials overlay B bytes [0,16K) (= k8 0..3 region).
__global__ __launch_bounds__(128, 3) void gemm_topk_kernel() {
    extern __shared__ char sm[];
    uint4*  Bs = (uint4*)sm;
    float4* P4 = (float4*)sm;          // partial overlay: [(nf*2+mf)*32 + lane]

    const int tid  = threadIdx.x;
    const int w    = tid >> 5;
    const int lane = tid & 31;
    const int mf   = w & 1;
    const int kh   = w >> 1;
    const int g    = lane >> 2;
    const int t4   = lane & 3;
    const int mtile = blockIdx.x;

    // A in registers: own m-frag, own k-half (8 k8 slabs)
    uint4 a_regs[8];
#pragma unroll
    for (int k8h = 0; k8h < 8; k8h++)
        a_regs[k8h] = g_xA[(size_t)mtile * 1024 + (mf * 16 + kh * 8 + k8h) * 32 + lane];

    // initial B(0) load (full 64KB)
    {
        const uint4* src = g_yB;
        for (int i = tid; i < 4096; i += 128) {
            unsigned s = (unsigned)__cvta_generic_to_shared(Bs + i);
            asm volatile("cp.async.cg.shared.global [%0], [%1], 16;" :: "r"(s), "l"(src + i));
        }
        asm volatile("cp.async.commit_group;" ::: "memory");
    }

    float tvA[10], tvB[10]; int tiA[10], tiB[10];
#pragma unroll
    for (int q = 0; q < 10; q++) {
        tvA[q] = tvB[q] = -__int_as_float(0x7f800000);
        tiA[q] = tiB[q] = 0x7fffffff;
    }

    for (int t = 0; t < NT_Y; t++) {
        asm volatile("cp.async.wait_group 0;" ::: "memory");
        __syncthreads();                           // B(t) fully resident; P region free

        float acc[16][4];
#pragma unroll
        for (int nf = 0; nf < 16; nf++)
#pragma unroll
            for (int q = 0; q < 4; q++) acc[nf][q] = 0.0f;

#pragma unroll
        for (int k8h = 0; k8h < 8; k8h++) {
            uint4 a = a_regs[k8h];
            const uint4* Bk = Bs + ((kh * 8 + k8h) * 8) * 32;
#pragma unroll
            for (int p = 0; p < 8; p++) {
                uint4 bb = Bk[p * 32 + lane];
                mma_tf32(acc[2*p],     a, bb.x, bb.y);
                mma_tf32(acc[2*p + 1], a, bb.z, bb.w);
            }
        }
        __syncthreads();                           // B(t) consumed

        const uint4* srcN = g_yB + (size_t)(t + 1) * 4096;
        if (kh == 1) {
            // dump partials into B bytes [0,16K) — conflict-free float4
#pragma unroll
            for (int nf = 0; nf < 16; nf++)
                P4[(nf * 2 + mf) * 32 + lane] =
                    make_float4(acc[nf][0], acc[nf][1], acc[nf][2], acc[nf][3]);
        }
        if (t + 1 < NT_Y) {                        // G1: prefetch B(t+1) k8 4..15 (48KB)
            for (int i = 1024 + tid; i < 4096; i += 128) {
                unsigned s = (unsigned)__cvta_generic_to_shared(Bs + i);
                asm volatile("cp.async.cg.shared.global [%0], [%1], 16;" :: "r"(s), "l"(srcN + i));
            }
            asm volatile("cp.async.commit_group;" ::: "memory");
        }
        __syncthreads();                           // partials visible

        if (kh == 0) {
            int n0 = t * 128 + t4 * 2;
#pragma unroll
            for (int nf = 0; nf < 16; nf++) {
                float4 pp = P4[(nf * 2 + mf) * 32 + lane];
                float v0 = acc[nf][0] + pp.x;
                float v1 = acc[nf][1] + pp.y;
                float v2 = acc[nf][2] + pp.z;
                float v3 = acc[nf][3] + pp.w;
                int j0 = n0 + nf * 8;
                if (v0 > tvA[9] && j0 < NYC)     insert10(tvA, tiA, v0, j0);
                if (v1 > tvA[9] && j0 + 1 < NYC) insert10(tvA, tiA, v1, j0 + 1);
                if (v2 > tvB[9] && j0 < NYC)     insert10(tvB, tiB, v2, j0);
                if (v3 > tvB[9] && j0 + 1 < NYC) insert10(tvB, tiB, v3, j0 + 1);
            }
        }
        __syncthreads();                           // partial reads done -> region free

        if (t + 1 < NT_Y) {                        // G2: prefetch B(t+1) k8 0..3 (16KB)
            for (int i = tid; i < 1024; i += 128) {
                unsigned s = (unsigned)__cvta_generic_to_shared(Bs + i);
                asm volatile("cp.async.cg.shared.global [%0], [%1], 16;" :: "r"(s), "l"(srcN + i));
            }
            asm volatile("cp.async.commit_group;" ::: "memory");
        }
    }

    if (kh == 0) {
        int mA = mtile * 32 + mf * 16 + g;
        int mB = mA + 8;
#pragma unroll
        for (int q = 0; q < 10; q++) {
            g_candI[mA * NCAND + t4 * 10 + q] = tiA[q];
            g_candI[mB * NCAND + t4 * 10 + q] = tiB[q];
        }
    }
}

// ---------------- exact fp32 rescore (bitwise-identical chain) + softmax + COO ----------------
__global__ __launch_bounds__(128) void rescore_kernel(float* __restrict__ out) {
    extern __shared__ float rs[];
    float* xrow  = rs;                        // 128
    float* yrows = rs + 128;                  // 40 * 129 (pitch 129 -> conflict-free)
    float* vals  = yrows + 40 * 129;          // 40
    int*   cols  = (int*)(vals + 40);         // 40   (total 5368 floats = 21472 B)

    const int m = blockIdx.x;
    const int tid = threadIdx.x;

    if (tid < 128) xrow[tid] = g_x32[m * CDIM + tid];
    if (tid < 40)  cols[tid] = g_candI[m * NCAND + tid];
    __syncthreads();

    for (int i = tid; i < 40 * 32; i += 128) {
        int c = i >> 5, p = i & 31;
        float4 v = *(const float4*)&g_y32[(size_t)cols[c] * CDIM + p * 4];
        float* dst = &yrows[c * 129 + p * 4];
        dst[0] = v.x; dst[1] = v.y; dst[2] = v.z; dst[3] = v.w;
    }
    __syncthreads();

    if (tid < 40) {
        float s = 0.0f;
        const float* yr = &yrows[tid * 129];
#pragma unroll 16
        for (int k = 0; k < 128; k++) s = fmaf(xrow[k], yr[k], s);
        vals[tid] = s;
    }
    __syncthreads();

    if (tid == 0) {
        float tv[10]; int tix[10];
#pragma unroll
        for (int q = 0; q < 10; q++) { tv[q] = -__int_as_float(0x7f800000); tix[q] = 0x7fffffff; }
        for (int c = 0; c < 40; c++) {
            float v = vals[c]; int j = cols[c];
            if (v > tv[9] || (v == tv[9] && j < tix[9])) insert10(tv, tix, v, j);
        }
        float mx = tv[0];
        float e[10], sum = 0.0f;
#pragma unroll
        for (int q = 0; q < 10; q++) { e[q] = expf((tv[q] - mx) * INV_TAU); sum += e[q]; }
        float inv = 1.0f / sum;
#pragma unroll
        for (int q = 0; q < 10; q++) {
            out[m * 10 + q]           = e[q] * inv;
            out[NXK + m * 10 + q]     = (float)m;
            out[2 * NXK + m * 10 + q] = (float)tix[q];
        }
    }
}

// ---------------- launch ----------------
extern "C" void kernel_launch(void* const* d_in, const int* in_sizes, int n_in,
                              void* d_out, int out_size) {
    const float* fx = (const float*)d_in[0];
    const float* fy = (const float*)d_in[1];
    if (n_in >= 2 && in_sizes[0] == NYC * CDIM && in_sizes[1] == NXC * CDIM) {
        const float* t = fx; fx = fy; fy = t;
    }
    float* outF = (float*)d_out;

    cudaFuncSetAttribute(gemm_topk_kernel,
                         cudaFuncAttributeMaxDynamicSharedMemorySize, 65536);
    cudaFuncSetAttribute(rescore_kernel,
                         cudaFuncAttributeMaxDynamicSharedMemorySize, RESCORE_SMEM);

    norm_x_kernel<<<NXC / 8, 256>>>(fx);                                  // launch 1
    norm_y_kernel<<<NY_PAD / 8, 256>>>(fy);                               // launch 2
    pack_xy_frag<<<(NPACK_X + NPACK_Y + 255) / 256, 256>>>();             // launch 3
    gemm_topk_kernel<<<MTILES, 128, 65536>>>();                           // launch 4 (ncu target)
    rescore_kernel<<<NXC, 128, RESCORE_SMEM>>>(outF);                     // launch 5
}